// round 13
// baseline (speedup 1.0000x reference)
#include <cuda_runtime.h>

#define NB 32
#define CI 64
#define LT 300
#define V  25
#define KD 192

typedef unsigned long long ull;
typedef unsigned int uint;

// pre-swizzled W A-fragments: [Mt(12)][ks(8)][lane(32)][4] tf32 bits
__device__ __align__(16) uint g_Wfrag[12 * 8 * 32 * 4];
// pre-swizzled GEMM2 B-fragments: [ks(10)][t(4)][lane(32)] -> (b0,b1) tf32 bits
__device__ __align__(16) ull  g_A2frag[10 * 4 * 32];
// BN constants: [inv(64), bias(64)]
__device__ __align__(16) float g_bn[2 * CI];

__device__ __forceinline__ uint f2tf(float f){
    uint u; asm("cvt.rna.tf32.f32 %0,%1;" : "=r"(u) : "f"(f)); return u;
}
__device__ __forceinline__ ull pack2u(uint lo, uint hi){
    ull r; asm("mov.b64 %0,{%1,%2};" : "=l"(r) : "r"(lo), "r"(hi)); return r;
}
__device__ __forceinline__ void unpack2u(ull v, uint& lo, uint& hi){
    asm("mov.b64 {%0,%1},%2;" : "=r"(lo), "=r"(hi) : "l"(v));
}
__device__ __forceinline__ void mma_tf32(float& d0, float& d1, float& d2, float& d3,
                                         uint a0, uint a1, uint a2, uint a3,
                                         uint b0, uint b1){
    asm volatile("mma.sync.aligned.m16n8k8.row.col.f32.tf32.tf32.f32 "
                 "{%0,%1,%2,%3},{%4,%5,%6,%7},{%8,%9},{%0,%1,%2,%3};"
                 : "+f"(d0), "+f"(d1), "+f"(d2), "+f"(d3)
                 : "r"(a0), "r"(a1), "r"(a2), "r"(a3), "r"(b0), "r"(b1));
}

// ---------- kernel 0: one-time fragment/constant setup (1 block) ----------
__global__ __launch_bounds__(256) void setup_kernel(
    const float* __restrict__ A,
    const float* __restrict__ W,
    const float* __restrict__ gamma,
    const float* __restrict__ beta,
    const float* __restrict__ mean,
    const float* __restrict__ var)
{
    const int t = threadIdx.x;
    if (t < CI){
        float inv = gamma[t] * rsqrtf(var[t] + 1e-3f);
        g_bn[t]      = inv;
        g_bn[CI + t] = beta[t] - mean[t]*inv;
    }
    // W fragments: A1[row=k][col=c] = W[c][k]
    for (int idx = t; idx < 12*8*32*4; idx += 256){
        int j    = idx & 3;
        int lane = (idx >> 2) & 31;
        int ks   = (idx >> 7) & 7;
        int mt   = idx >> 10;
        int r  = mt*16 + (lane >> 2) + (j & 1)*8;
        int cc = ks*8  + (lane & 3)  + (j >> 1)*4;
        g_Wfrag[idx] = f2tf(W[cc*KD + r]);
    }
    // GEMM2 B fragments over padded K: C in [0,80), row C -> (p=C/26, v=C%26)
    for (int idx = t; idx < 10*4*32; idx += 256){
        int lane = idx & 31;
        int tt   = (idx >> 5) & 3;
        int ks   = idx >> 7;
        int lq = lane & 3, lg = lane >> 2;
        int C0 = ks*8 + lq, C1 = C0 + 4;
        int wc = tt*8 + lg;
        uint b0 = 0, b1 = 0;
        if (wc < V){
            int p0 = C0/26, v0 = C0 - 26*p0;
            if (C0 < 78 && v0 < V) b0 = f2tf(A[(p0*V + v0)*V + wc]);
            int p1 = C1/26, v1 = C1 - 26*p1;
            if (C1 < 78 && v1 < V) b1 = f2tf(A[(p1*V + v1)*V + wc]);
        }
        g_A2frag[idx] = pack2u(b0, b1);
    }
}

// ---------- main: fused window + dual tf32 GEMM + BN + ReLU + residual ----------
// block = (n, m-pair). 256 threads (8 warps), 2 blocks/SM.
// smem: xw [64][72] | Yr [128][84] | xres [64][50]
#define TPB 256
#define XW_OFF 0
#define YR_OFF (XW_OFF + 64*72)
#define XR_OFF (YR_OFF + 128*84)
#define SM_WORDS (XR_OFF + 64*50)
#define MAIN_SMEM (SM_WORDS * 4)      // 74240 B

__global__ __launch_bounds__(TPB, 2) void main_kernel(
    const float* __restrict__ x,
    float* __restrict__ out)
{
    extern __shared__ float sm[];
    uint*  smu = (uint*)sm;

    const int tid  = threadIdx.x;
    const int wid  = tid >> 5;
    const int lane = tid & 31;
    const int lg   = lane >> 2;
    const int lq   = lane & 3;
    const int n    = blockIdx.x / 150;
    const int mp   = blockIdx.x % 150;
    const int m0   = mp * 2;

    // zero pads: xw cols 25, 51, 52..55; Yr cols 78..79
    if (tid < 64){
        sm[XW_OFF + tid*72 + 25] = 0.f;
        sm[XW_OFF + tid*72 + 51] = 0.f;
        float4 z = make_float4(0.f, 0.f, 0.f, 0.f);
        *(float4*)(sm + XW_OFF + tid*72 + 52) = z;
    }
    sm[YR_OFF + (tid >> 1)*84 + 78 + (tid & 1)] = 0.f;

    // ---- fused 9-tap window staging: xw (tf32) + xres (raw residual rows) ----
    {
        const float* xb = x + (size_t)n*CI*LT*V;
        #pragma unroll 1
        for (int col = tid; col < CI*V; col += TPB){
            int c = (col * 5243) >> 17;          // col / 25
            int v = col - 25*c;
            const float* xp = xb + (size_t)c*(LT*V) + v;
            float xv[10];
            #pragma unroll
            for (int j = 0; j < 10; j++){
                int l = m0 - 8 + j;
                xv[j] = (l >= 0) ? __ldg(xp + (size_t)l*V) : 0.f;
            }
            float s0 = 0.f, s1 = 0.f;
            #pragma unroll
            for (int j = 0; j < 9; j++) s0 += xv[j];
            #pragma unroll
            for (int j = 1; j < 10; j++) s1 += xv[j];
            smu[XW_OFF + c*72 + v]      = f2tf(s0);
            smu[XW_OFF + c*72 + 26 + v] = f2tf(s1);
            sm[XR_OFF + c*50 + v]       = xv[8];   // x at l = m0
            sm[XR_OFF + c*50 + 25 + v]  = xv[9];   // x at l = m0+1
        }
    }
    __syncthreads();

    // ---- GEMM1: Y[192, 56] = W^T @ xw ; warp (mw, nw): 3 Mtiles x (4|3) Ntiles ----
    {
        const int mw = wid >> 1;
        const int nw = wid & 1;
        const int nNt = nw ? 3 : 4;
        const int ntBase = nw * 4;
        const int mtB = mw * 3;

        float acc[3][4][4];
        #pragma unroll
        for (int i = 0; i < 3; i++)
            #pragma unroll
            for (int t = 0; t < 4; t++)
                #pragma unroll
                for (int e = 0; e < 4; e++) acc[i][t][e] = 0.f;

        uint4 aC[3], aN[3];
        #pragma unroll
        for (int i = 0; i < 3; i++)
            aC[i] = *(const uint4*)(g_Wfrag + (((mtB + i)*8 + 0)*32 + lane)*4);

        #pragma unroll
        for (int ks = 0; ks < 8; ks++){
            int ksn = (ks + 1) & 7;
            #pragma unroll
            for (int i = 0; i < 3; i++)
                aN[i] = *(const uint4*)(g_Wfrag + (((mtB + i)*8 + ksn)*32 + lane)*4);

            uint b0[4], b1[4];
            #pragma unroll
            for (int t = 0; t < 4; t++){
                if (t < nNt){
                    int nt = ntBase + t;
                    b0[t] = smu[XW_OFF + (ks*8 + lq    )*72 + nt*8 + lg];
                    b1[t] = smu[XW_OFF + (ks*8 + lq + 4)*72 + nt*8 + lg];
                }
            }
            #pragma unroll
            for (int i = 0; i < 3; i++)
                #pragma unroll
                for (int t = 0; t < 4; t++)
                    if (t < nNt)
                        mma_tf32(acc[i][t][0], acc[i][t][1], acc[i][t][2], acc[i][t][3],
                                 aC[i].x, aC[i].y, aC[i].z, aC[i].w, b0[t], b1[t]);
            #pragma unroll
            for (int i = 0; i < 3; i++) aC[i] = aN[i];
        }

        // scatter Y into GEMM2 A-fragment layout: row = co*2+m, col = p*26+v.
        #pragma unroll
        for (int i = 0; i < 3; i++){
            int k1  = (mtB + i)*16 + lg;
            int co1 = k1/3,  pp1 = k1 - co1*3;
            int k2  = k1 + 8;
            int co2 = k2/3,  pp2 = k2 - co2*3;
            #pragma unroll
            for (int t = 0; t < 4; t++)
                if (t < nNt){
                    int col0 = (ntBase + t)*8 + 2*lq;
                    if (col0 < 52){
                        int m  = (col0 >= 26) ? 1 : 0;
                        int v  = col0 - 26*m;
                        *(ull*)(sm + YR_OFF + (co1*2 + m)*84 + pp1*26 + v) =
                            pack2u(f2tf(acc[i][t][0]), f2tf(acc[i][t][1]));
                        *(ull*)(sm + YR_OFF + (co2*2 + m)*84 + pp2*26 + v) =
                            pack2u(f2tf(acc[i][t][2]), f2tf(acc[i][t][3]));
                    }
                }
        }
    }
    __syncthreads();

    // ---- GEMM2: T[128, 32] = Yr[128, 80] @ A2pad[80, 32]; warp = Mtile ----
    {
        float acc2[4][4];
        #pragma unroll
        for (int t = 0; t < 4; t++)
            #pragma unroll
            for (int e = 0; e < 4; e++) acc2[t][e] = 0.f;

        const int R = wid*16 + lg;
        const uint* yr = smu + YR_OFF;

        ull bcur[4];
        #pragma unroll
        for (int t = 0; t < 4; t++) bcur[t] = g_A2frag[t*32 + lane];

        #pragma unroll
        for (int ks = 0; ks < 10; ks++){
            int ksn = (ks + 1 < 10) ? ks + 1 : 0;
            ull bnx[4];
            #pragma unroll
            for (int t = 0; t < 4; t++) bnx[t] = g_A2frag[(ksn*4 + t)*32 + lane];

            int C0 = ks*8 + lq;
            int C1 = C0 + 4;
            uint a0 = yr[ R     *84 + C0];
            uint a1 = yr[(R + 8)*84 + C0];
            uint a2 = yr[ R     *84 + C1];
            uint a3 = yr[(R + 8)*84 + C1];

            #pragma unroll
            for (int t = 0; t < 4; t++){
                uint b0, b1; unpack2u(bcur[t], b0, b1);
                mma_tf32(acc2[t][0], acc2[t][1], acc2[t][2], acc2[t][3],
                         a0, a1, a2, a3, b0, b1);
            }
            #pragma unroll
            for (int t = 0; t < 4; t++) bcur[t] = bnx[t];
        }

        // epilogue: BN + ReLU + residual (from smem) + ReLU
        #pragma unroll
        for (int t = 0; t < 4; t++){
            int wc = t*8 + 2*lq;
            #pragma unroll
            for (int j = 0; j < 2; j++){
                int Rr = wid*16 + lg + 8*j;
                int co = Rr >> 1;
                int ml = Rr & 1;
                int m2 = m0 + ml;
                float d0 = acc2[t][2*j];
                float d1 = acc2[t][2*j + 1];
                float iv = __ldg(g_bn + co);
                float bb = __ldg(g_bn + 64 + co);
                const float* xr = sm + XR_OFF + co*50 + ml*25;
                size_t base = ((size_t)(n*CI + co)*LT + m2)*V;
                if (wc < V){
                    float r0 = fmaxf(fmaf(d0, iv, bb), 0.f);
                    out[base + wc] = fmaxf(r0 + xr[wc], 0.f);
                }
                if (wc + 1 < V){
                    float r1 = fmaxf(fmaf(d1, iv, bb), 0.f);
                    out[base + wc + 1] = fmaxf(r1 + xr[wc + 1], 0.f);
                }
            }
        }
    }
}

extern "C" void kernel_launch(void* const* d_in, const int* in_sizes, int n_in,
                              void* d_out, int out_size) {
    const float* x     = (const float*)d_in[0];
    const float* A     = (const float*)d_in[1];
    const float* W     = (const float*)d_in[2];
    const float* gamma = (const float*)d_in[3];
    const float* beta  = (const float*)d_in[4];
    const float* mean  = (const float*)d_in[5];
    const float* var   = (const float*)d_in[6];
    float* out = (float*)d_out;

    setup_kernel<<<1, 256>>>(A, W, gamma, beta, mean, var);

    cudaFuncSetAttribute(main_kernel, cudaFuncAttributeMaxDynamicSharedMemorySize, MAIN_SMEM);
    main_kernel<<<NB * 150, TPB, MAIN_SMEM>>>(x, out);
}

// round 14
// speedup vs baseline: 1.1860x; 1.1860x over previous
#include <cuda_runtime.h>

#define NB 32
#define CI 64
#define LT 300
#define V  25
#define KD 192

typedef unsigned long long ull;
typedef unsigned int uint;

// xwin (tf32 bits), layout [n][mpair(150)][c(64)][52]  (cols 25 & 51 stay 0)
__device__ float g_xwin2[(size_t)NB * 150 * CI * 52];
// pre-swizzled W A-fragments: [Mt(12)][ks(8)][lane(32)][4] tf32 bits
__device__ __align__(16) uint g_Wfrag[12 * 8 * 32 * 4];
// pre-swizzled GEMM2 B-fragments: [ks(10)][t(4)][lane(32)] -> (b0,b1) tf32 bits
__device__ __align__(16) ull  g_A2frag[10 * 4 * 32];
// BN constants: [inv(64), bias(64)]
__device__ __align__(16) float g_bn[2 * CI];

__device__ __forceinline__ uint f2tf(float f){
    uint u; asm("cvt.rna.tf32.f32 %0,%1;" : "=r"(u) : "f"(f)); return u;
}
__device__ __forceinline__ ull pack2u(uint lo, uint hi){
    ull r; asm("mov.b64 %0,{%1,%2};" : "=l"(r) : "r"(lo), "r"(hi)); return r;
}
__device__ __forceinline__ void unpack2u(ull v, uint& lo, uint& hi){
    asm("mov.b64 {%0,%1},%2;" : "=r"(lo), "=r"(hi) : "l"(v));
}
__device__ __forceinline__ void mma_tf32(float& d0, float& d1, float& d2, float& d3,
                                         uint a0, uint a1, uint a2, uint a3,
                                         uint b0, uint b1){
    asm volatile("mma.sync.aligned.m16n8k8.row.col.f32.tf32.tf32.f32 "
                 "{%0,%1,%2,%3},{%4,%5,%6,%7},{%8,%9},{%0,%1,%2,%3};"
                 : "+f"(d0), "+f"(d1), "+f"(d2), "+f"(d3)
                 : "r"(a0), "r"(a1), "r"(a2), "r"(a3), "r"(b0), "r"(b1));
}
__device__ __forceinline__ unsigned smem_u32(const void* p){
    unsigned a;
    asm("{ .reg .u64 t; cvta.to.shared.u64 t, %1; cvt.u32.u64 %0, t; }" : "=r"(a) : "l"(p));
    return a;
}

// ---------- kernel 1: window sum (L sliced x12) + one-time setup (block 0) ----------
#define WCG 8
#define WLQ 25          // l per slice (12 slices)
#define WTH (WCG * V)

__global__ __launch_bounds__(WTH) void win_kernel(
    const float* __restrict__ x,
    const float* __restrict__ A,
    const float* __restrict__ W,
    const float* __restrict__ gamma,
    const float* __restrict__ beta,
    const float* __restrict__ mean,
    const float* __restrict__ var)
{
    const int b = blockIdx.x;
    const int t = threadIdx.x;

    if (b == 0){
        if (t < CI){
            float inv = gamma[t] * rsqrtf(var[t] + 1e-3f);
            g_bn[t]      = inv;
            g_bn[CI + t] = beta[t] - mean[t]*inv;
        }
        // W fragments: A1[row=k][col=c] = W[c][k]
        for (int idx = t; idx < 12*8*32*4; idx += WTH){
            int j    = idx & 3;
            int lane = (idx >> 2) & 31;
            int ks   = (idx >> 7) & 7;
            int mt   = idx >> 10;
            int r  = mt*16 + (lane >> 2) + (j & 1)*8;
            int cc = ks*8  + (lane & 3)  + (j >> 1)*4;
            g_Wfrag[idx] = f2tf(W[cc*KD + r]);
        }
        // GEMM2 B fragments over padded K: C in [0,80), row C -> (p=C/26, v=C%26)
        for (int idx = t; idx < 10*4*32; idx += WTH){
            int lane = idx & 31;
            int tt   = (idx >> 5) & 3;
            int ks   = idx >> 7;
            int lq = lane & 3, lg = lane >> 2;
            int C0 = ks*8 + lq, C1 = C0 + 4;
            int wc = tt*8 + lg;
            uint b0 = 0, b1 = 0;
            if (wc < V){
                int p0 = C0/26, v0 = C0 - 26*p0;
                if (C0 < 78 && v0 < V) b0 = f2tf(A[(p0*V + v0)*V + wc]);
                int p1 = C1/26, v1 = C1 - 26*p1;
                if (C1 < 78 && v1 < V) b1 = f2tf(A[(p1*V + v1)*V + wc]);
            }
            g_A2frag[idx] = pack2u(b0, b1);
        }
    }

    const int n  = b / 96;
    const int r  = b - n*96;
    const int cg = r / 12;
    const int q  = r - cg*12;
    const int cl = t / V;
    const int v  = t - cl * V;
    const int c  = cg * WCG + cl;
    const int l0 = q * WLQ;

    const float* xp = x + ((size_t)(n * CI + c) * LT) * V + v;
    float* opb = g_xwin2 + ((size_t)n * 150 * CI + c) * 52 + v;

    float ring[9];
    #pragma unroll
    for (int j = 0; j < 9; j++) ring[j] = 0.f;
    float s = 0.f;

    // cover l0-8 .. l0+24 in 4 chunks of 9; stores gated to [l0, l0+25)
    #pragma unroll 1
    for (int base = 0; base < 36; base += 9) {
        #pragma unroll
        for (int j = 0; j < 9; j++) {
            int l = l0 - 8 + base + j;
            float nv = (l >= 0 && l < LT) ? xp[(size_t)l * V] : 0.f;
            s += nv - ring[j];
            ring[j] = nv;
            if (l >= l0 && l < l0 + WLQ)
                opb[(size_t)(l >> 1) * (CI*52) + (l & 1)*26] = __uint_as_float(f2tf(s));
        }
    }
}

// ---------- kernel 2: fused dual tf32 GEMM + BN + ReLU + residual ----------
// block = (n, m-pair). 256 threads (8 warps), 2 blocks/SM.
// smem: xw [64][72] | Yr [128][84] | xres [64][50]
#define TPB 256
#define XW_OFF 0
#define YR_OFF (XW_OFF + 64*72)
#define XR_OFF (YR_OFF + 128*84)
#define SM_WORDS (XR_OFF + 64*50)
#define MAIN_SMEM (SM_WORDS * 4)      // 74240 B

__global__ __launch_bounds__(TPB, 2) void main_kernel(
    const float* __restrict__ x,
    float* __restrict__ out)
{
    extern __shared__ float sm[];
    uint*  smu = (uint*)sm;

    const int tid  = threadIdx.x;
    const int wid  = tid >> 5;
    const int lane = tid & 31;
    const int lg   = lane >> 2;
    const int lq   = lane & 3;
    const int n    = blockIdx.x / 150;
    const int mp   = blockIdx.x % 150;
    const int m0   = mp * 2;

    // ---- staging: xw (group A) then xres (group B, consumed after GEMM1) ----
    {
        const unsigned sb = smem_u32(sm);
        const char* srcX = (const char*)(g_xwin2 + ((size_t)n*150 + mp) * (CI*52));
        #pragma unroll
        for (int j = 0; j < 4; j++){
            int idx = j*TPB + tid;
            if (idx < 832){
                int c  = idx / 13;
                int jj = idx - c*13;
                asm volatile("cp.async.ca.shared.global [%0], [%1], 16;"
                             :: "r"(sb + (unsigned)(c*288 + jj*16)),
                                "l"(srcX + (size_t)c*208 + jj*16));
            }
        }
        asm volatile("cp.async.commit_group;");
        // xres: rows m0, m0+1 for all c = 50 contiguous floats per c (8B aligned)
        const char* srcR = (const char*)(x + ((size_t)(n*CI)*LT + m0)*V);
        #pragma unroll
        for (int j = 0; j < 7; j++){
            int idx = j*TPB + tid;
            if (idx < 1600){
                int c  = idx / 25;
                int jj = idx - c*25;
                asm volatile("cp.async.ca.shared.global [%0], [%1], 8;"
                             :: "r"(sb + XR_OFF*4 + (unsigned)(idx*8)),
                                "l"(srcR + (size_t)c*(LT*V*4) + (size_t)jj*8));
            }
        }
        asm volatile("cp.async.commit_group;");
    }
    // zero xw pad cols 52..55 and Yr pad cols 78..79
    if (tid < 64){
        float4 z = make_float4(0.f, 0.f, 0.f, 0.f);
        *(float4*)(sm + XW_OFF + tid*72 + 52) = z;
    }
    sm[YR_OFF + (tid >> 1)*84 + 78 + (tid & 1)] = 0.f;
    asm volatile("cp.async.wait_group 1;");   // xw ready; xres still in flight
    __syncthreads();

    // ---- GEMM1: Y[192, 56] = W^T @ xw ; warp (mw, nw): 3 Mtiles x (4|3) Ntiles ----
    {
        const int mw = wid >> 1;
        const int nw = wid & 1;
        const int nNt = nw ? 3 : 4;
        const int ntBase = nw * 4;
        const int mtB = mw * 3;

        float acc[3][4][4];
        #pragma unroll
        for (int i = 0; i < 3; i++)
            #pragma unroll
            for (int t = 0; t < 4; t++)
                #pragma unroll
                for (int e = 0; e < 4; e++) acc[i][t][e] = 0.f;

        uint4 aC[3], aN[3];
        #pragma unroll
        for (int i = 0; i < 3; i++)
            aC[i] = *(const uint4*)(g_Wfrag + (((mtB + i)*8 + 0)*32 + lane)*4);

        #pragma unroll
        for (int ks = 0; ks < 8; ks++){
            int ksn = (ks + 1) & 7;
            #pragma unroll
            for (int i = 0; i < 3; i++)
                aN[i] = *(const uint4*)(g_Wfrag + (((mtB + i)*8 + ksn)*32 + lane)*4);

            uint b0[4], b1[4];
            #pragma unroll
            for (int t = 0; t < 4; t++){
                if (t < nNt){
                    int nt = ntBase + t;
                    b0[t] = smu[XW_OFF + (ks*8 + lq    )*72 + nt*8 + lg];
                    b1[t] = smu[XW_OFF + (ks*8 + lq + 4)*72 + nt*8 + lg];
                }
            }
            #pragma unroll
            for (int i = 0; i < 3; i++)
                #pragma unroll
                for (int t = 0; t < 4; t++)
                    if (t < nNt)
                        mma_tf32(acc[i][t][0], acc[i][t][1], acc[i][t][2], acc[i][t][3],
                                 aC[i].x, aC[i].y, aC[i].z, aC[i].w, b0[t], b1[t]);
            #pragma unroll
            for (int i = 0; i < 3; i++) aC[i] = aN[i];
        }

        // scatter Y into GEMM2 A-fragment layout: row = co*2+m, col = p*26+v.
        #pragma unroll
        for (int i = 0; i < 3; i++){
            int k1  = (mtB + i)*16 + lg;
            int co1 = k1/3,  pp1 = k1 - co1*3;
            int k2  = k1 + 8;
            int co2 = k2/3,  pp2 = k2 - co2*3;
            #pragma unroll
            for (int t = 0; t < 4; t++)
                if (t < nNt){
                    int col0 = (ntBase + t)*8 + 2*lq;
                    if (col0 < 52){
                        int m  = (col0 >= 26) ? 1 : 0;
                        int v  = col0 - 26*m;
                        *(ull*)(sm + YR_OFF + (co1*2 + m)*84 + pp1*26 + v) =
                            pack2u(f2tf(acc[i][t][0]), f2tf(acc[i][t][1]));
                        *(ull*)(sm + YR_OFF + (co2*2 + m)*84 + pp2*26 + v) =
                            pack2u(f2tf(acc[i][t][2]), f2tf(acc[i][t][3]));
                    }
                }
        }
    }
    asm volatile("cp.async.wait_group 0;");   // xres ready
    __syncthreads();

    // ---- GEMM2: T[128, 32] = Yr[128, 80] @ A2pad[80, 32]; warp = Mtile ----
    {
        float acc2[4][4];
        #pragma unroll
        for (int t = 0; t < 4; t++)
            #pragma unroll
            for (int e = 0; e < 4; e++) acc2[t][e] = 0.f;

        const int R = wid*16 + lg;
        const uint* yr = smu + YR_OFF;

        ull bcur[4];
        #pragma unroll
        for (int t = 0; t < 4; t++) bcur[t] = g_A2frag[t*32 + lane];

        #pragma unroll
        for (int ks = 0; ks < 10; ks++){
            int ksn = (ks + 1 < 10) ? ks + 1 : 0;
            ull bnx[4];
            #pragma unroll
            for (int t = 0; t < 4; t++) bnx[t] = g_A2frag[(ksn*4 + t)*32 + lane];

            int C0 = ks*8 + lq;
            int C1 = C0 + 4;
            uint a0 = yr[ R     *84 + C0];
            uint a1 = yr[(R + 8)*84 + C0];
            uint a2 = yr[ R     *84 + C1];
            uint a3 = yr[(R + 8)*84 + C1];

            #pragma unroll
            for (int t = 0; t < 4; t++){
                uint b0, b1; unpack2u(bcur[t], b0, b1);
                mma_tf32(acc2[t][0], acc2[t][1], acc2[t][2], acc2[t][3],
                         a0, a1, a2, a3, b0, b1);
            }
            #pragma unroll
            for (int t = 0; t < 4; t++) bcur[t] = bnx[t];
        }

        // epilogue: BN + ReLU + residual (from smem) + ReLU
        #pragma unroll
        for (int t = 0; t < 4; t++){
            int wc = t*8 + 2*lq;
            #pragma unroll
            for (int j = 0; j < 2; j++){
                int Rr = wid*16 + lg + 8*j;
                int co = Rr >> 1;
                int ml = Rr & 1;
                int m2 = m0 + ml;
                float d0 = acc2[t][2*j];
                float d1 = acc2[t][2*j + 1];
                float iv = __ldg(g_bn + co);
                float bb = __ldg(g_bn + 64 + co);
                const float* xr = sm + XR_OFF + co*50 + ml*25;
                size_t base = ((size_t)(n*CI + co)*LT + m2)*V;
                if (wc < V){
                    float r0 = fmaxf(fmaf(d0, iv, bb), 0.f);
                    out[base + wc] = fmaxf(r0 + xr[wc], 0.f);
                }
                if (wc + 1 < V){
                    float r1 = fmaxf(fmaf(d1, iv, bb), 0.f);
                    out[base + wc + 1] = fmaxf(r1 + xr[wc + 1], 0.f);
                }
            }
        }
    }
}

extern "C" void kernel_launch(void* const* d_in, const int* in_sizes, int n_in,
                              void* d_out, int out_size) {
    const float* x     = (const float*)d_in[0];
    const float* A     = (const float*)d_in[1];
    const float* W     = (const float*)d_in[2];
    const float* gamma = (const float*)d_in[3];
    const float* beta  = (const float*)d_in[4];
    const float* mean  = (const float*)d_in[5];
    const float* var   = (const float*)d_in[6];
    float* out = (float*)d_out;

    win_kernel<<<NB * 8 * 12, WTH>>>(x, A, W, gamma, beta, mean, var);

    cudaFuncSetAttribute(main_kernel, cudaFuncAttributeMaxDynamicSharedMemorySize, MAIN_SMEM);
    main_kernel<<<NB * 150, TPB, MAIN_SMEM>>>(x, out);
}